// round 17
// baseline (speedup 1.0000x reference)
#include <cuda_runtime.h>
#include <math.h>

// ----------------------------------------------------------------------------
// QuantumBranch, single flag-gated PERSISTENT kernel (round 17).
// expz0(t) = P(c) + s*Q(c), c = cos(pi t), s = sin(pi t); P deg 12, Q deg 11.
// R16 WIN (12.8 -> 11.0us) confirmed the persistent/pipelined structure.
// Remaining cap: occ 44.7% -- the 608-block grid is only 4 blocks/SM.
// This round (single A/B change): 912 blocks = 6 blocks/SM x 152, still one
// wave, with __launch_bounds__(256,6) (42-reg budget; main-loop liveness
// ~41 regs: 25 coefficients + 8 pipeline + indices -> no main-loop spills).
// Warps/SM 32 -> 48 should cover the ~600-cyc LDG window per the latency
// model (12 warps/SMSP x ~126 issue-cyc > 600).
// Block 0 computes 25 monomial coefficients (parallel preamble) -> flag;
// others prefetch their first float4 pre-gate, spin once, then Horner.
// ----------------------------------------------------------------------------

#define NSAMP 25
#define NHARM 12
#define THREADS 256
#define BLOCKS 912
#define PI_F  3.14159265358979323846f
#define TWO_PI_F 6.28318530717958647692f

__device__ float g_coef[25];   // p[0..12], q[0..11]
__device__ int   g_flag;       // 0 -> coefficients not yet published

struct cf { float re, im; };

__device__ __forceinline__ void gate1q(cf* s, int wire,
    float u00r, float u00i, float u01r, float u01i,
    float u10r, float u10i, float u11r, float u11i)
{
    const int str = 4 >> wire;
    #pragma unroll
    for (int k = 0; k < 8; k++) {
        if (k & str) continue;
        cf a = s[k], b = s[k + str];
        s[k].re       = u00r*a.re - u00i*a.im + u01r*b.re - u01i*b.im;
        s[k].im       = u00r*a.im + u00i*a.re + u01r*b.im + u01i*b.re;
        s[k + str].re = u10r*a.re - u10i*a.im + u11r*b.re - u11i*b.im;
        s[k + str].im = u10r*a.im + u10i*a.re + u11r*b.im + u11i*b.re;
    }
}

__device__ __forceinline__ void cnot(cf* s, int ctrl, int tgt)
{
    const int sc = 4 >> ctrl, st = 4 >> tgt;
    #pragma unroll
    for (int k = 0; k < 8; k++) {
        if (!(k & sc) || (k & st)) continue;
        cf tmp = s[k]; s[k] = s[k + st]; s[k + st] = tmp;
    }
}

__device__ void ansatz_pre(cf* s, const float* thc, const float* ths, int layer)
{
    #pragma unroll
    for (int i = 0; i < 3; i++) {
        int j = layer * 9 + i * 3;
        float c, z;
        c = thc[j + 0]; z = ths[j + 0];
        gate1q(s, i, c, -z, 0.f, 0.f, 0.f, 0.f, c, z);          // RZ
        c = thc[j + 1]; z = ths[j + 1];
        gate1q(s, i, c, 0.f, 0.f, -z, 0.f, -z, c, 0.f);         // RX
        c = thc[j + 2]; z = ths[j + 2];
        gate1q(s, i, c, -z, 0.f, 0.f, 0.f, 0.f, c, z);          // RZ
    }
    cnot(s, 0, 1); cnot(s, 1, 2); cnot(s, 2, 0);
}

// Block-0-only preamble: circuit samples -> DFT -> monomial coefficients.
__device__ void do_precompute(const float* __restrict__ theta, int tid)
{
    __shared__ float thc[27], ths[27];
    __shared__ float twc[NSAMP], tws[NSAMP];
    __shared__ float fsamp[NSAMP];
    __shared__ float ca[NHARM + 1], cb[NHARM + 1];
    __shared__ float Tc[13 * 13];
    __shared__ float Uc[12 * 13];

    const int lane = tid & 31;

    if (tid < 27)
        __sincosf(0.5f * theta[tid], &ths[tid], &thc[tid]);
    else if (tid >= 32 && tid < 64) {
        float v0 = (lane == 0) ? 1.f : 0.f;
        float v1 = (lane == 1) ? 1.f : 0.f;
        if (lane < 13) { Tc[0 * 13 + lane] = v0; Tc[1 * 13 + lane] = v1; }
        #pragma unroll
        for (int k = 2; k <= 12; k++) {
            float up = __shfl_up_sync(0xFFFFFFFFu, v1, 1);
            if (lane == 0) up = 0.f;
            float v2 = fmaf(2.f, up, -v0);
            if (lane < 13) Tc[k * 13 + lane] = v2;
            v0 = v1; v1 = v2;
        }
        v0 = (lane == 0) ? 1.f : 0.f;
        v1 = (lane == 1) ? 2.f : 0.f;
        if (lane < 13) { Uc[0 * 13 + lane] = v0; Uc[1 * 13 + lane] = v1; }
        #pragma unroll
        for (int m = 2; m <= 11; m++) {
            float up = __shfl_up_sync(0xFFFFFFFFu, v1, 1);
            if (lane == 0) up = 0.f;
            float v2 = fmaf(2.f, up, -v0);
            if (lane < 13) Uc[m * 13 + lane] = v2;
            v0 = v1; v1 = v2;
        }
    }
    else if (tid >= 64 && tid < 64 + NSAMP) {
        int j = tid - 64;
        __sincosf(TWO_PI_F * (float)j * (1.0f / 25.0f), &tws[j], &twc[j]);
    }
    __syncthreads();

    if (tid < NSAMP) {
        float tt = 2.0f * (float)tid / 25.0f;
        float fc[3], fs_[3];
        #pragma unroll
        for (int i = 0; i < 3; i++)
            __sincosf(0.5f * PI_F * tt * (float)(i + 1), &fs_[i], &fc[i]);

        cf s[8];
        #pragma unroll
        for (int k = 0; k < 8; k++) { s[k].re = 0.f; s[k].im = 0.f; }
        s[0].re = 1.f;
        ansatz_pre(s, thc, ths, 0);
        #pragma unroll
        for (int i = 0; i < 3; i++)
            gate1q(s, i, fc[i], 0.f, -fs_[i], 0.f, fs_[i], 0.f, fc[i], 0.f);
        ansatz_pre(s, thc, ths, 1);
        #pragma unroll
        for (int i = 0; i < 3; i++)
            gate1q(s, i, fc[i], 0.f, -fs_[i], 0.f, fs_[i], 0.f, fc[i], 0.f);
        ansatz_pre(s, thc, ths, 2);
        float e = 0.f;
        #pragma unroll
        for (int k = 0; k < 8; k++) {
            float p = s[k].re*s[k].re + s[k].im*s[k].im;
            e += (k < 4) ? p : -p;   // Z on qubit 0
        }
        fsamp[tid] = e;
    }
    __syncthreads();

    if (tid < NSAMP) {
        float sum = 0.f;
        if (tid == 0) {
            for (int m = 0; m < NSAMP; m++) sum += fsamp[m];
            ca[0] = sum * (1.0f / 25.0f);
            cb[0] = 0.f;
        } else if (tid <= NHARM) {
            int r = 0;
            for (int m = 0; m < NSAMP; m++) {
                sum = fmaf(fsamp[m], twc[r], sum);
                r += tid; if (r >= 25) r -= 25;
            }
            ca[tid] = sum * (2.0f / 25.0f);
        } else {
            int k = tid - NHARM, r = 0;
            for (int m = 0; m < NSAMP; m++) {
                sum = fmaf(fsamp[m], tws[r], sum);
                r += k; if (r >= 25) r -= 25;
            }
            cb[k] = sum * (2.0f / 25.0f);
        }
    }
    __syncthreads();

    if (tid < 13) {
        float s = 0.f;
        #pragma unroll
        for (int k = 0; k < 13; k++)
            s = fmaf(ca[k], Tc[k * 13 + tid], s);
        g_coef[tid] = s;                       // p[tid]
        __threadfence();
    } else if (tid >= 16 && tid < 28) {
        int j = tid - 16;
        float s = 0.f;
        #pragma unroll
        for (int m = 0; m < 12; m++)
            s = fmaf(cb[m + 1], Uc[m * 13 + j], s);
        g_coef[13 + j] = s;                    // q[j]
        __threadfence();
    }
    __syncthreads();
    if (tid == 0)
        atomicExch(&g_flag, 1);                // release the grid
}

__device__ __forceinline__ float eval_poly(float tt, const float* p,
                                           const float* q)
{
    float s, c;
    __sincosf(PI_F * tt, &s, &c);
    float P = p[12];
    #pragma unroll
    for (int j = 11; j >= 0; j--) P = fmaf(P, c, p[j]);
    float Q = q[11];
    #pragma unroll
    for (int j = 10; j >= 0; j--) Q = fmaf(Q, c, q[j]);
    return fmaf(s, Q, P);
}

__global__ void __launch_bounds__(THREADS, 6)
fused_kernel(const float* __restrict__ theta,
             const float* __restrict__ t,
             float* __restrict__ out, int n)
{
    const int tid = threadIdx.x;
    const int idx = blockIdx.x * THREADS + tid;
    const int stride = BLOCKS * THREADS;
    const int nvec = n >> 2;
    const float4* in4 = reinterpret_cast<const float4*>(t);
    float4* out4 = reinterpret_cast<float4*>(out);

    // prefetch first iteration BEFORE the gate (overlaps block 0's preamble)
    float4 cur;
    bool have = idx < nvec;
    if (have) cur = __ldg(in4 + idx);

    if (blockIdx.x == 0) {
        do_precompute(theta, tid);
    } else {
        if (tid == 0) {
            while (atomicAdd(&g_flag, 0) == 0)
                __nanosleep(64);
            __threadfence();
        }
        __syncthreads();
    }

    // coefficients once per thread
    float p[13], q[12];
    #pragma unroll
    for (int j = 0; j < 13; j++) p[j] = __ldg(&g_coef[j]);
    #pragma unroll
    for (int j = 0; j < 12; j++) q[j] = __ldg(&g_coef[13 + j]);

    // software-pipelined grid-stride loop: prefetch v+stride, compute v
    for (int v = idx; v < nvec; v += stride) {
        const int vn = v + stride;
        float4 nxt;
        if (vn < nvec) nxt = __ldg(in4 + vn);
        float4 ov;
        ov.x = eval_poly(cur.x, p, q);
        ov.y = eval_poly(cur.y, p, q);
        ov.z = eval_poly(cur.z, p, q);
        ov.w = eval_poly(cur.w, p, q);
        out4[v] = ov;
        cur = nxt;
    }

    // tail (n not a multiple of 4)
    for (int i = (nvec << 2) + idx; i < n; i += stride)
        out[i] = eval_poly(t[i], p, q);
}

extern "C" void kernel_launch(void* const* d_in, const int* in_sizes, int n_in,
                              void* d_out, int out_size)
{
    const float* t;
    const float* theta;
    if (n_in >= 2 && in_sizes[0] == 27 && in_sizes[1] != 27) {
        theta = (const float*)d_in[0];
        t     = (const float*)d_in[1];
    } else {
        t     = (const float*)d_in[0];
        theta = (const float*)d_in[1];
    }
    float* out = (float*)d_out;
    const int n = out_size;

    fused_kernel<<<BLOCKS, THREADS>>>(theta, t, out, n);
}